// round 4
// baseline (speedup 1.0000x reference)
#include <cuda_runtime.h>
#include <cuda_fp16.h>
#include <cstdint>

#define NB 1024
#define NT 256
#define NE 300
#define LOG2E 1.4426950408889634

// ---------------- static device scratch (no allocations allowed) ----------------
__device__ float g_M[NT * NT];       // M[t][f] = sum_e TE[e][t] * Wf[f][e]
__device__ float g_G2[NT * NT];      // (M M^T) * log2(e)
__device__ float g_v2[NT];           // (M b_f) * log2(e)
__device__ float g_c2;               // (b_f . b_f) * log2(e)
__device__ __align__(16) __half g_E[67108864];  // 128MB: exp weights per batch
__device__ float g_u[NB * NT];       // s_j * rtheta_j
__device__ float g_S[NB];            // sum_j s_j
__device__ float g_ar[NB * NT];      // ave_req
__device__ float g_aw[NB * NT];      // ave_wsdl

__device__ __forceinline__ float fast_exp2(float x) {
    float y; asm("ex2.approx.f32 %0, %1;" : "=f"(y) : "f"(x)); return y;
}
__device__ __forceinline__ float fast_rcp(float x) {
    float y; asm("rcp.approx.f32 %0, %1;" : "=f"(y) : "f"(x)); return y;
}

// ---------------- precompute M (fp64 accumulate for accuracy) ----------------
__global__ void k_M(const float* __restrict__ te, const float* __restrict__ wf) {
    __shared__ float tesh[NE];
    int t = blockIdx.x, f = threadIdx.x;
    for (int e = f; e < NE; e += NT) tesh[e] = te[e * NT + t];
    __syncthreads();
    const float* wrow = wf + f * NE;
    double acc = 0.0;
    for (int e = 0; e < NE; e++) acc += (double)tesh[e] * (double)wrow[e];
    g_M[t * NT + f] = (float)acc;
}

// ---------------- precompute G2 = (M M^T)*log2e, v2, c2 ----------------
__global__ void k_G(const float* __restrict__ bf) {
    __shared__ float mi[NT];
    __shared__ float bsh[NT];
    int i = blockIdx.x, j = threadIdx.x;
    mi[j] = g_M[i * NT + j];
    if (i == 0) bsh[j] = bf[j];
    __syncthreads();
    const float* mj = g_M + j * NT;
    double acc = 0.0;
    for (int k = 0; k < NT; k++) acc += (double)mi[k] * (double)mj[k];
    g_G2[i * NT + j] = (float)(acc * LOG2E);
    if (i == 0) {
        double av = 0.0;
        for (int k = 0; k < NT; k++) av += (double)mj[k] * (double)bsh[k];
        g_v2[j] = (float)(av * LOG2E);
        if (j == 0) {
            double cc = 0.0;
            for (int k = 0; k < NT; k++) cc += (double)bsh[k] * (double)bsh[k];
            g_c2 = (float)(cc * LOG2E);
        }
    }
}

// ---------------- main: per-batch softmax structure ----------------
// A2[r][c] = w_c * (r_r * G2[r][c]) + (p2[r] + base_c)   (all in log2 domain)
// col stats over r (axis=1), then s_j = sum_c E[j][c] * (1/Z[c])
__global__ void __launch_bounds__(NT) k_main(const float* __restrict__ req,
                                             const float* __restrict__ wsdl) {
    __shared__ float rs[NT];
    __shared__ float p2[NT];
    __shared__ __align__(16) float Rr[NT];
    __shared__ float sred[8];
    int b = blockIdx.x, c = threadIdx.x;

    float w_c = wsdl[b * NT + c];
    float r_c = req[b * NT + c];
    float v2c = g_v2[c];
    rs[c] = r_c;
    p2[c] = r_c * v2c;
    __syncthreads();
    float base = fmaf(w_c, v2c, g_c2);
    const float* Gc = g_G2 + c;

    // pass 1: exact column max
    float mx = -1e30f;
#pragma unroll 8
    for (int r = 0; r < NT; r++) {
        float a = fmaf(w_c * rs[r], Gc[r * NT], p2[r] + base);
        mx = fmaxf(mx, a);
    }

    // pass 2: exp2, column sum Z, store fp16 weights (layout E[r][c], coalesced)
    float Z = 0.0f;
    __half* Ec = g_E + (size_t)b * (NT * NT) + c;
#pragma unroll 8
    for (int r = 0; r < NT; r++) {
        float a = fmaf(w_c * rs[r], Gc[r * NT], p2[r] + base);
        float e = fast_exp2(a - mx);
        Z += e;
        Ec[(size_t)r * NT] = __float2half(e);
    }
    Rr[c] = fast_rcp(Z);
    __syncthreads();

    // pass 3: row sums with per-column normalizers (thread c owns row c)
    const uint4* er = (const uint4*)(g_E + (size_t)b * (NT * NT) + (size_t)c * NT);
    const float4* R4 = (const float4*)Rr;
    float s = 0.0f;
#pragma unroll 8
    for (int q = 0; q < NT / 8; q++) {
        uint4 u4 = er[q];
        float2 e0 = __half22float2(*(__half2*)&u4.x);
        float2 e1 = __half22float2(*(__half2*)&u4.y);
        float2 e2 = __half22float2(*(__half2*)&u4.z);
        float2 e3 = __half22float2(*(__half2*)&u4.w);
        float4 ra = R4[2 * q], rb = R4[2 * q + 1];
        s = fmaf(e0.x, ra.x, s); s = fmaf(e0.y, ra.y, s);
        s = fmaf(e1.x, ra.z, s); s = fmaf(e1.y, ra.w, s);
        s = fmaf(e2.x, rb.x, s); s = fmaf(e2.y, rb.y, s);
        s = fmaf(e3.x, rb.z, s); s = fmaf(e3.y, rb.w, s);
    }
    g_u[b * NT + c] = s * r_c;

    // block-reduce S = sum_j s_j
    float v = s;
#pragma unroll
    for (int o = 16; o; o >>= 1) v += __shfl_down_sync(0xffffffffu, v, o);
    if ((c & 31) == 0) sred[c >> 5] = v;
    __syncthreads();
    if (c == 0) {
        float S = 0.0f;
#pragma unroll
        for (int w = 0; w < 8; w++) S += sred[w];
        g_S[b] = S;
    }
}

// ---------------- finalize: ave_req / ave_wsdl via vec-mat with M (8 batches/CTA) --
__global__ void __launch_bounds__(NT) k_ave(const float* __restrict__ req,
                                            const float* __restrict__ bf) {
    __shared__ float rsh[8 * NT];
    __shared__ float ush[8 * NT];
    int bb = blockIdx.x * 8;
    int k = threadIdx.x;
    for (int idx = k; idx < 8 * NT; idx += NT) {
        int b = idx >> 8, t = idx & 255;
        rsh[idx] = req[(bb + b) * NT + t];
        ush[idx] = g_u[(bb + b) * NT + t];
    }
    __syncthreads();
    float ar[8] = {0, 0, 0, 0, 0, 0, 0, 0};
    float aw[8] = {0, 0, 0, 0, 0, 0, 0, 0};
#pragma unroll 4
    for (int t = 0; t < NT; t++) {
        float m = g_M[t * NT + k];
#pragma unroll
        for (int b = 0; b < 8; b++) {
            ar[b] = fmaf(rsh[b * NT + t], m, ar[b]);
            aw[b] = fmaf(ush[b * NT + t], m, aw[b]);
        }
    }
    float bfk = bf[k];
    const float invT = 1.0f / (float)NT;
#pragma unroll
    for (int b = 0; b < 8; b++) {
        g_ar[(bb + b) * NT + k] = fmaf(ar[b], invT, bfk);
        g_aw[(bb + b) * NT + k] = (aw[b] + g_S[bb + b] * bfk) * invT;
    }
}

// ---------------- cosine similarity * 3 ----------------
__global__ void k_cos(float* __restrict__ out) {
    int b = blockIdx.x, l = threadIdx.x;
    float num = 0.0f, d1 = 0.0f, d2 = 0.0f;
    for (int k = l; k < NT; k += 32) {
        float a = g_ar[b * NT + k], w = g_aw[b * NT + k];
        num = fmaf(a, w, num);
        d1 = fmaf(a, a, d1);
        d2 = fmaf(w, w, d2);
    }
#pragma unroll
    for (int o = 16; o; o >>= 1) {
        num += __shfl_down_sync(0xffffffffu, num, o);
        d1  += __shfl_down_sync(0xffffffffu, d1, o);
        d2  += __shfl_down_sync(0xffffffffu, d2, o);
    }
    if (l == 0) {
        float denom = fmaxf(sqrtf(d1) * sqrtf(d2), 1e-8f);
        out[b] = 3.0f * num / denom;
    }
}

extern "C" void kernel_launch(void* const* d_in, const int* in_sizes, int n_in,
                              void* d_out, int out_size) {
    const float* req  = (const float*)d_in[0];   // [B,T]
    const float* wsdl = (const float*)d_in[1];   // [B,T]
    const float* te   = (const float*)d_in[2];   // [E,T]
    const float* wf   = (const float*)d_in[3];   // [T,E]
    const float* bf   = (const float*)d_in[4];   // [T]
    float* out = (float*)d_out;                  // [B]

    k_M<<<NT, NT>>>(te, wf);
    k_G<<<NT, NT>>>(bf);
    k_main<<<NB, NT>>>(req, wsdl);
    k_ave<<<NB / 8, NT>>>(req, bf);
    k_cos<<<NB, 32>>>(out);
}